// round 1
// baseline (speedup 1.0000x reference)
#include <cuda_runtime.h>
#include <math.h>
#include <stdint.h>

// ---------------------------------------------------------------------------
// MultiScaleDeformableAttention (Deformable-DETR style), fp32.
//   BS=2, nq=nv=20197, E=256, NH=8, NL=4, NP=4, d=32
// Pipeline:
//   1) g_V   = value @ Wv + bv                      (SGEMM, N=256)
//   2) g_SO  = query @ Wso + bso                    (SGEMM, N=256)
//   3) g_AWL = query @ Waw + baw                    (SGEMM, N=128)
//   4) g_TMP = bilinear-sample + softmax(aw) reduce (1 warp per (b,q,head))
//   5) out   = g_TMP @ Wo + bo + query              (SGEMM + residual epilogue)
// ---------------------------------------------------------------------------

#define NQ    20197
#define BSZ   2
#define EDIM  256
#define NHEAD 8
#define NLVL  4
#define NPTS  4

// Scratch (allocation-free rule: __device__ globals)
__device__ float g_V  [BSZ * NQ * EDIM];
__device__ float g_SO [BSZ * NQ * EDIM];
__device__ float g_AWL[BSZ * NQ * NHEAD * NLVL * NPTS];
__device__ float g_TMP[BSZ * NQ * EDIM];

// ---------------------------------------------------------------------------
// SGEMM: C[M,N] = A[M,K] @ B[K,N] + bias[N] (+ res[M,N] if res != nullptr)
// Row-major. BM=BN=128, BK=8, 256 threads, 8x8 per thread.
// Requires: K % 8 == 0, N % 128 == 0 (true here: K=256, N in {128,256}).
// ---------------------------------------------------------------------------
__global__ __launch_bounds__(256) void sgemm128(
    const float* __restrict__ A, const float* __restrict__ B,
    const float* __restrict__ bias, const float* __restrict__ res,
    float* __restrict__ C, int M, int N, int K)
{
    __shared__ float As[8][128];   // transposed A tile: As[k][m]
    __shared__ float Bs[8][128];   // Bs[k][n]

    const int tid  = threadIdx.x;
    const int brow = blockIdx.y * 128;
    const int bcol = blockIdx.x * 128;

    // A-tile load map: 128 rows x 8 cols, one float4 per thread
    const int arow = tid >> 1;
    const int acol = (tid & 1) << 2;
    // B-tile load map: 8 rows x 128 cols, one float4 per thread
    const int brB = tid >> 5;
    const int bcB = (tid & 31) << 2;
    // compute map: 16x16 thread grid, each thread 8 rows x 8 cols
    const int tr = (tid >> 4) << 3;
    const int tc = (tid & 15) << 3;

    float acc[8][8];
#pragma unroll
    for (int i = 0; i < 8; i++)
#pragma unroll
        for (int j = 0; j < 8; j++) acc[i][j] = 0.f;

    const bool aval = (brow + arow) < M;
    const float* Aptr = A + (size_t)(brow + arow) * K + acol;
    const float* Bptr = B + (size_t)brB * N + bcol + bcB;

    for (int k0 = 0; k0 < K; k0 += 8) {
        float4 av = aval ? *(const float4*)(Aptr + k0)
                         : make_float4(0.f, 0.f, 0.f, 0.f);
        float4 bv = *(const float4*)(Bptr + (size_t)k0 * N);

        As[acol + 0][arow] = av.x;
        As[acol + 1][arow] = av.y;
        As[acol + 2][arow] = av.z;
        As[acol + 3][arow] = av.w;
        *(float4*)&Bs[brB][bcB] = bv;
        __syncthreads();

#pragma unroll
        for (int k = 0; k < 8; k++) {
            float a[8], bb[8];
#pragma unroll
            for (int i = 0; i < 8; i++) a[i] = As[k][tr + i];
#pragma unroll
            for (int j = 0; j < 8; j++) bb[j] = Bs[k][tc + j];
#pragma unroll
            for (int i = 0; i < 8; i++)
#pragma unroll
                for (int j = 0; j < 8; j++)
                    acc[i][j] = fmaf(a[i], bb[j], acc[i][j]);
        }
        __syncthreads();
    }

#pragma unroll
    for (int i = 0; i < 8; i++) {
        const int r = brow + tr + i;
        if (r < M) {
#pragma unroll
            for (int j = 0; j < 8; j += 4) {
                const int c = bcol + tc + j;
                float4 o;
                o.x = acc[i][j + 0] + bias[c + 0];
                o.y = acc[i][j + 1] + bias[c + 1];
                o.z = acc[i][j + 2] + bias[c + 2];
                o.w = acc[i][j + 3] + bias[c + 3];
                if (res) {
                    const float4 rv = *(const float4*)(res + (size_t)r * N + c);
                    o.x += rv.x; o.y += rv.y; o.z += rv.z; o.w += rv.w;
                }
                *(float4*)(C + (size_t)r * N + c) = o;
            }
        }
    }
}

// ---------------------------------------------------------------------------
// Sampler: one block per (b,q); warp h handles head h; lane = channel (d=32).
//   - softmax over 16 (l,p) logits per head via warp shuffles
//   - loc_x*W - 0.5 == rx*W + so_x - 0.5 (offset_norm cancels)
//   - 4 zero-padded bilinear corners, each a coalesced 128B gather
// ---------------------------------------------------------------------------
__global__ __launch_bounds__(256) void msda_sample(
    const float* __restrict__ V, const float* __restrict__ SO,
    const float* __restrict__ AWL, const float* __restrict__ refp,
    const int* __restrict__ shapes, const int* __restrict__ starts,
    float* __restrict__ out)
{
    const int bq   = blockIdx.x;                 // 0 .. BSZ*NQ-1
    const int b    = bq / NQ;
    const int h    = threadIdx.x >> 5;           // head = warp id
    const int lane = threadIdx.x & 31;           // channel

    // This head's 32 sampling-offset values: (l*NP+p)*2 + c, c in {x,y}
    const float myso = SO[(size_t)bq * EDIM + h * 32 + lane];

    // Softmax over the 16 attention logits of this head (lanes 0..15)
    float logit = (lane < 16)
        ? AWL[(size_t)bq * (NHEAD * NLVL * NPTS) + h * 16 + lane]
        : -1e30f;
    float m = logit;
#pragma unroll
    for (int off = 8; off; off >>= 1)
        m = fmaxf(m, __shfl_xor_sync(0xffffffffu, m, off));
    float e = (lane < 16) ? expf(logit - m) : 0.f;
    float ssum = e;
#pragma unroll
    for (int off = 8; off; off >>= 1)
        ssum += __shfl_xor_sync(0xffffffffu, ssum, off);
    const float aw = e / ssum;   // valid on lanes 0..15 (only those are shuffled from)

    float acc = 0.f;
    const float* refq = refp + (size_t)bq * NLVL * 2;

#pragma unroll
    for (int l = 0; l < NLVL; l++) {
        const int H = shapes[2 * l + 0];
        const int W = shapes[2 * l + 1];
        const int s = starts[l];
        const float rx = refq[2 * l + 0];
        const float ry = refq[2 * l + 1];
        const float* vb = V + ((size_t)b * NQ + s) * EDIM + h * 32 + lane;

#pragma unroll
        for (int p = 0; p < NPTS; p++) {
            const int sp = l * NPTS + p;
            const float sox = __shfl_sync(0xffffffffu, myso, sp * 2 + 0, 32);
            const float soy = __shfl_sync(0xffffffffu, myso, sp * 2 + 1, 32);
            const float a   = __shfl_sync(0xffffffffu, aw,   sp,         32);

            const float x = fmaf(rx, (float)W, sox) - 0.5f;
            const float y = fmaf(ry, (float)H, soy) - 0.5f;
            const float xf = floorf(x), yf = floorf(y);
            const int x0 = (int)xf, y0 = (int)yf;
            const float wx1 = x - xf, wx0 = 1.f - wx1;
            const float wy1 = y - yf, wy0 = 1.f - wy1;

            const bool vx0 = (x0 >= 0)     && (x0 < W);
            const bool vx1 = (x0 + 1 >= 0) && (x0 + 1 < W);
            const bool vy0 = (y0 >= 0)     && (y0 < H);
            const bool vy1 = (y0 + 1 >= 0) && (y0 + 1 < H);

            float sum = 0.f;
            if (vy0) {
                const size_t rowb = (size_t)(y0 * W) * EDIM;
                if (vx0) sum = fmaf(wx0 * wy0, vb[rowb + (size_t)x0 * EDIM], sum);
                if (vx1) sum = fmaf(wx1 * wy0, vb[rowb + (size_t)(x0 + 1) * EDIM], sum);
            }
            if (vy1) {
                const size_t rowb = (size_t)((y0 + 1) * W) * EDIM;
                if (vx0) sum = fmaf(wx0 * wy1, vb[rowb + (size_t)x0 * EDIM], sum);
                if (vx1) sum = fmaf(wx1 * wy1, vb[rowb + (size_t)(x0 + 1) * EDIM], sum);
            }
            acc = fmaf(a, sum, acc);
        }
    }
    out[(size_t)bq * EDIM + h * 32 + lane] = acc;
}

// ---------------------------------------------------------------------------
// Launch
// ---------------------------------------------------------------------------
extern "C" void kernel_launch(void* const* d_in, const int* in_sizes, int n_in,
                              void* d_out, int out_size)
{
    const float* query  = (const float*)d_in[0];
    const float* value  = (const float*)d_in[1];
    const float* refp   = (const float*)d_in[2];
    const int*   shapes = (const int*)  d_in[3];
    const int*   starts = (const int*)  d_in[4];
    const float* Wv  = (const float*)d_in[5];
    const float* bv  = (const float*)d_in[6];
    const float* Wso = (const float*)d_in[7];
    const float* bso = (const float*)d_in[8];
    const float* Waw = (const float*)d_in[9];
    const float* baw = (const float*)d_in[10];
    const float* Wo  = (const float*)d_in[11];
    const float* bo  = (const float*)d_in[12];
    float* out = (float*)d_out;

    const int M = in_sizes[0] / EDIM;   // BSZ * NQ = 40394

    float *pV, *pSO, *pAWL, *pTMP;
    cudaGetSymbolAddress((void**)&pV,   g_V);
    cudaGetSymbolAddress((void**)&pSO,  g_SO);
    cudaGetSymbolAddress((void**)&pAWL, g_AWL);
    cudaGetSymbolAddress((void**)&pTMP, g_TMP);

    const dim3 gN256(2, (M + 127) / 128);
    const dim3 gN128(1, (M + 127) / 128);

    sgemm128<<<gN256, 256>>>(value, Wv, bv, nullptr, pV,   M, 256, 256);
    sgemm128<<<gN256, 256>>>(query, Wso, bso, nullptr, pSO, M, 256, 256);
    sgemm128<<<gN128, 256>>>(query, Waw, baw, nullptr, pAWL, M, 128, 256);
    msda_sample<<<M, 256>>>(pV, pSO, pAWL, refp, shapes, starts, pTMP);
    sgemm128<<<gN256, 256>>>(pTMP, Wo, bo, query, out, M, 256, 256);
}

// round 2
// speedup vs baseline: 1.2717x; 1.2717x over previous
#include <cuda_runtime.h>
#include <math.h>
#include <stdint.h>

// ---------------------------------------------------------------------------
// MultiScaleDeformableAttention (Deformable-DETR style), fp32.
//   BS=2, nq=nv=20197, E=256, NH=8, NL=4, NP=4, d=32
// Pipeline:
//   1) g_V   = value @ Wv + bv                      (SGEMM, N=256)
//   2) g_SO  = query @ Wso + bso                    (SGEMM, N=256)
//   3) g_AWL = query @ Waw + baw                    (SGEMM, N=128)
//   4) g_TMP = bilinear-sample + softmax(aw) reduce (vectorized 2-phase)
//   5) out   = g_TMP @ Wo + bo + query              (SGEMM + residual epilogue)
// ---------------------------------------------------------------------------

#define NQ    20197
#define BSZ   2
#define EDIM  256
#define NHEAD 8
#define NLVL  4
#define NPTS  4

// Scratch (allocation-free rule: __device__ globals)
__device__ float g_V  [BSZ * NQ * EDIM];
__device__ float g_SO [BSZ * NQ * EDIM];
__device__ float g_AWL[BSZ * NQ * NHEAD * NLVL * NPTS];
__device__ float g_TMP[BSZ * NQ * EDIM];

// ---------------------------------------------------------------------------
// SGEMM: C[M,N] = A[M,K] @ B[K,N] + bias[N] (+ res[M,N] if res != nullptr)
// Row-major. BM=BN=128, BK=8, 256 threads, 8x8 per thread. (unchanged)
// ---------------------------------------------------------------------------
__global__ __launch_bounds__(256) void sgemm128(
    const float* __restrict__ A, const float* __restrict__ B,
    const float* __restrict__ bias, const float* __restrict__ res,
    float* __restrict__ C, int M, int N, int K)
{
    __shared__ float As[8][128];   // transposed A tile: As[k][m]
    __shared__ float Bs[8][128];   // Bs[k][n]

    const int tid  = threadIdx.x;
    const int brow = blockIdx.y * 128;
    const int bcol = blockIdx.x * 128;

    const int arow = tid >> 1;
    const int acol = (tid & 1) << 2;
    const int brB = tid >> 5;
    const int bcB = (tid & 31) << 2;
    const int tr = (tid >> 4) << 3;
    const int tc = (tid & 15) << 3;

    float acc[8][8];
#pragma unroll
    for (int i = 0; i < 8; i++)
#pragma unroll
        for (int j = 0; j < 8; j++) acc[i][j] = 0.f;

    const bool aval = (brow + arow) < M;
    const float* Aptr = A + (size_t)(brow + arow) * K + acol;
    const float* Bptr = B + (size_t)brB * N + bcol + bcB;

    for (int k0 = 0; k0 < K; k0 += 8) {
        float4 av = aval ? *(const float4*)(Aptr + k0)
                         : make_float4(0.f, 0.f, 0.f, 0.f);
        float4 bv = *(const float4*)(Bptr + (size_t)k0 * N);

        As[acol + 0][arow] = av.x;
        As[acol + 1][arow] = av.y;
        As[acol + 2][arow] = av.z;
        As[acol + 3][arow] = av.w;
        *(float4*)&Bs[brB][bcB] = bv;
        __syncthreads();

#pragma unroll
        for (int k = 0; k < 8; k++) {
            float a[8], bb[8];
#pragma unroll
            for (int i = 0; i < 8; i++) a[i] = As[k][tr + i];
#pragma unroll
            for (int j = 0; j < 8; j++) bb[j] = Bs[k][tc + j];
#pragma unroll
            for (int i = 0; i < 8; i++)
#pragma unroll
                for (int j = 0; j < 8; j++)
                    acc[i][j] = fmaf(a[i], bb[j], acc[i][j]);
        }
        __syncthreads();
    }

#pragma unroll
    for (int i = 0; i < 8; i++) {
        const int r = brow + tr + i;
        if (r < M) {
#pragma unroll
            for (int j = 0; j < 8; j += 4) {
                const int c = bcol + tc + j;
                float4 o;
                o.x = acc[i][j + 0] + bias[c + 0];
                o.y = acc[i][j + 1] + bias[c + 1];
                o.z = acc[i][j + 2] + bias[c + 2];
                o.w = acc[i][j + 3] + bias[c + 3];
                if (res) {
                    const float4 rv = *(const float4*)(res + (size_t)r * N + c);
                    o.x += rv.x; o.y += rv.y; o.z += rv.z; o.w += rv.w;
                }
                *(float4*)(C + (size_t)r * N + c) = o;
            }
        }
    }
}

// ---------------------------------------------------------------------------
// Sampler v2: two-phase, float4 channels, 4 heads per warp.
// Block = 256 threads handles 4 queries (bq).
//
// Phase A (precompute): 1 thread per 2 (h,pt) pairs of one (bq,h).
//   - softmax over the head's 16 logits via width-8 xor-shuffles (2 vals/lane)
//   - bilinear corner row-indices (clamped) + corner weights * aw  -> smem
// Phase B (gather): warp = (bq, head-half); lane = 8*headsub + c4.
//   Per point: 2 broadcast LDS.128 + 4 LDG.128 (one 128B line per 8-lane
//   group) + 16 FFMA into a float4 accumulator.
// ---------------------------------------------------------------------------
__global__ __launch_bounds__(256) void msda_sample4(
    const float* __restrict__ V, const float* __restrict__ SO,
    const float* __restrict__ AWL, const float* __restrict__ refp,
    const int* __restrict__ shapes, const int* __restrict__ starts,
    float* __restrict__ out, int M)
{
    __shared__ int4   sOff[4][16][8];   // [bqLocal][pt][head]: 4 corner rows
    __shared__ float4 sW  [4][16][8];   // [bqLocal][pt][head]: 4 corner weights*aw

    const int tid = threadIdx.x;

    // -------------------- Phase A: precompute --------------------
    {
        const int wi  = tid << 1;            // pair index within block (0..511)
        const int bqL = wi >> 7;             // 0..3
        const int h   = (wi >> 4) & 7;       // head
        const int pt0 = wi & 15;             // even point index; this thread does pt0, pt0+1
        int bq = blockIdx.x * 4 + bqL;
        bq = min(bq, M - 1);                 // clamp for safe loads; store guarded in B

        // softmax over this head's 16 logits (8 lanes x 2 values, xor-reduce w=8)
        const float2 lg = *(const float2*)(AWL + (size_t)bq * 128 + h * 16 + pt0);
        float mx = fmaxf(lg.x, lg.y);
#pragma unroll
        for (int off = 4; off; off >>= 1)
            mx = fmaxf(mx, __shfl_xor_sync(0xffffffffu, mx, off));
        const float e0 = expf(lg.x - mx);
        const float e1 = expf(lg.y - mx);
        float sm = e0 + e1;
#pragma unroll
        for (int off = 4; off; off >>= 1)
            sm += __shfl_xor_sync(0xffffffffu, sm, off);
        const float inv = 1.f / sm;

        const int l = pt0 >> 2;              // pt pairs never straddle a level
        const int H = shapes[2 * l + 0];
        const int W = shapes[2 * l + 1];
        const int st = starts[l];
        const float2 rp = *(const float2*)(refp + ((size_t)bq * NLVL + l) * 2);
        const float4 so = *(const float4*)(SO + (size_t)bq * EDIM + h * 32 + pt0 * 2);

#pragma unroll
        for (int k = 0; k < 2; k++) {
            const int pt = pt0 + k;
            const float aw  = (k ? e1 : e0) * inv;
            const float sox = k ? so.z : so.x;
            const float soy = k ? so.w : so.y;

            const float x = fmaf(rp.x, (float)W, sox) - 0.5f;
            const float y = fmaf(rp.y, (float)H, soy) - 0.5f;
            const float xf = floorf(x), yf = floorf(y);
            const int x0 = (int)xf, y0 = (int)yf;
            const float wx1 = x - xf, wx0 = 1.f - wx1;
            const float wy1 = y - yf, wy0 = 1.f - wy1;

            const bool vx0 = (x0 >= 0) && (x0 < W);
            const bool vx1 = (x0 + 1 >= 0) && (x0 + 1 < W);
            const bool vy0 = (y0 >= 0) && (y0 < H);
            const bool vy1 = (y0 + 1 >= 0) && (y0 + 1 < H);

            const int cx0 = max(0, min(x0,     W - 1));
            const int cx1 = max(0, min(x0 + 1, W - 1));
            const int cy0 = max(0, min(y0,     H - 1));
            const int cy1 = max(0, min(y0 + 1, H - 1));

            int4 o;
            o.x = st + cy0 * W + cx0;
            o.y = st + cy0 * W + cx1;
            o.z = st + cy1 * W + cx0;
            o.w = st + cy1 * W + cx1;

            float4 w4;
            w4.x = (vx0 && vy0) ? wx0 * wy0 * aw : 0.f;
            w4.y = (vx1 && vy0) ? wx1 * wy0 * aw : 0.f;
            w4.z = (vx0 && vy1) ? wx0 * wy1 * aw : 0.f;
            w4.w = (vx1 && vy1) ? wx1 * wy1 * aw : 0.f;

            sOff[bqL][pt][h] = o;
            sW  [bqL][pt][h] = w4;
        }
    }
    __syncthreads();

    // -------------------- Phase B: gather --------------------
    const int warpId = tid >> 5;
    const int lane   = tid & 31;
    const int bqL    = warpId >> 1;                    // 0..3
    const int h      = ((warpId & 1) << 2) + (lane >> 3);  // head 0..7
    const int c4     = lane & 7;                       // float4 slot within head row
    const int bq     = blockIdx.x * 4 + bqL;
    if (bq >= M) return;
    const int b = bq / NQ;

    const float* vb = V + (size_t)b * NQ * EDIM + h * 32 + c4 * 4;

    float4 acc = make_float4(0.f, 0.f, 0.f, 0.f);
#pragma unroll
    for (int pt = 0; pt < 16; pt++) {
        const int4   o = sOff[bqL][pt][h];
        const float4 w = sW  [bqL][pt][h];

        const float4 v0 = *(const float4*)(vb + o.x * EDIM);
        const float4 v1 = *(const float4*)(vb + o.y * EDIM);
        const float4 v2 = *(const float4*)(vb + o.z * EDIM);
        const float4 v3 = *(const float4*)(vb + o.w * EDIM);

        acc.x = fmaf(w.x, v0.x, acc.x);
        acc.y = fmaf(w.x, v0.y, acc.y);
        acc.z = fmaf(w.x, v0.z, acc.z);
        acc.w = fmaf(w.x, v0.w, acc.w);

        acc.x = fmaf(w.y, v1.x, acc.x);
        acc.y = fmaf(w.y, v1.y, acc.y);
        acc.z = fmaf(w.y, v1.z, acc.z);
        acc.w = fmaf(w.y, v1.w, acc.w);

        acc.x = fmaf(w.z, v2.x, acc.x);
        acc.y = fmaf(w.z, v2.y, acc.y);
        acc.z = fmaf(w.z, v2.z, acc.z);
        acc.w = fmaf(w.z, v2.w, acc.w);

        acc.x = fmaf(w.w, v3.x, acc.x);
        acc.y = fmaf(w.w, v3.y, acc.y);
        acc.z = fmaf(w.w, v3.z, acc.z);
        acc.w = fmaf(w.w, v3.w, acc.w);
    }

    *(float4*)(out + (size_t)bq * EDIM + h * 32 + c4 * 4) = acc;
}

// ---------------------------------------------------------------------------
// Launch
// ---------------------------------------------------------------------------
extern "C" void kernel_launch(void* const* d_in, const int* in_sizes, int n_in,
                              void* d_out, int out_size)
{
    const float* query  = (const float*)d_in[0];
    const float* value  = (const float*)d_in[1];
    const float* refp   = (const float*)d_in[2];
    const int*   shapes = (const int*)  d_in[3];
    const int*   starts = (const int*)  d_in[4];
    const float* Wv  = (const float*)d_in[5];
    const float* bv  = (const float*)d_in[6];
    const float* Wso = (const float*)d_in[7];
    const float* bso = (const float*)d_in[8];
    const float* Waw = (const float*)d_in[9];
    const float* baw = (const float*)d_in[10];
    const float* Wo  = (const float*)d_in[11];
    const float* bo  = (const float*)d_in[12];
    float* out = (float*)d_out;

    const int M = in_sizes[0] / EDIM;   // BSZ * NQ = 40394

    float *pV, *pSO, *pAWL, *pTMP;
    cudaGetSymbolAddress((void**)&pV,   g_V);
    cudaGetSymbolAddress((void**)&pSO,  g_SO);
    cudaGetSymbolAddress((void**)&pAWL, g_AWL);
    cudaGetSymbolAddress((void**)&pTMP, g_TMP);

    const dim3 gN256(2, (M + 127) / 128);
    const dim3 gN128(1, (M + 127) / 128);

    sgemm128<<<gN256, 256>>>(value, Wv, bv, nullptr, pV,   M, 256, 256);
    sgemm128<<<gN256, 256>>>(query, Wso, bso, nullptr, pSO, M, 256, 256);
    sgemm128<<<gN128, 256>>>(query, Waw, baw, nullptr, pAWL, M, 128, 256);
    msda_sample4<<<(M + 3) / 4, 256>>>(pV, pSO, pAWL, refp, shapes, starts, pTMP, M);
    sgemm128<<<gN256, 256>>>(pTMP, Wo, bo, query, out, M, 256, 256);
}

// round 4
// speedup vs baseline: 2.2302x; 1.7537x over previous
#include <cuda_runtime.h>
#include <cuda_bf16.h>
#include <math.h>
#include <stdint.h>

// ---------------------------------------------------------------------------
// MultiScaleDeformableAttention, fp32 in/out.
// GEMMs via mma.sync bf16 (m16n8k16) with 3-term error compensation
// expressed as a single K=768 GEMM:  A' = [Ah|Ah|Al],  B't = [Bh|Bl|Bh].
//   BS=2, nq=nv=20197, E=256, NH=8, NL=4, NP=4, d=32
// ---------------------------------------------------------------------------

#define NQ    20197
#define BSZ   2
#define EDIM  256
#define NHEAD 8
#define NLVL  4
#define NPTS  4
#define MTOT  (BSZ * NQ)     // 40394

#define KP    768            // concatenated K
#define BK    32
#define NKIT  (KP / BK)      // 24
#define APAD  40             // smem row elems (80 bytes) -> conflict-free ldmatrix
#define ASZ   (128 * APAD)   // elems per stage per operand

// ------------------------------- scratch ------------------------------------
__device__ float g_V  [MTOT * EDIM];
__device__ float g_SO [MTOT * EDIM];
__device__ float g_AWL[MTOT * 128];
__device__ __nv_bfloat16 g_Aval[(size_t)MTOT * KP];
__device__ __nv_bfloat16 g_Aq  [(size_t)MTOT * KP];
__device__ __nv_bfloat16 g_Atmp[(size_t)MTOT * KP];
__device__ __nv_bfloat16 g_Bv [256 * KP];
__device__ __nv_bfloat16 g_Bso[256 * KP];
__device__ __nv_bfloat16 g_Baw[128 * KP];
__device__ __nv_bfloat16 g_Bo [256 * KP];

// -------------------------- small PTX helpers -------------------------------
__device__ __forceinline__ uint32_t smem_u32(const void* p) {
    uint32_t a;
    asm("{ .reg .u64 t; cvta.to.shared.u64 t, %1; cvt.u32.u64 %0, t; }"
        : "=r"(a) : "l"(p));
    return a;
}
__device__ __forceinline__ void cp_async16(uint32_t dst, const void* src) {
    asm volatile("cp.async.cg.shared.global [%0], [%1], 16;"
                 :: "r"(dst), "l"(src) : "memory");
}
__device__ __forceinline__ void cp_commit() {
    asm volatile("cp.async.commit_group;" ::: "memory");
}
template <int N>
__device__ __forceinline__ void cp_wait() {
    asm volatile("cp.async.wait_group %0;" :: "n"(N) : "memory");
}
__device__ __forceinline__ void ldmatrix_x4(uint32_t* r, uint32_t addr) {
    asm volatile("ldmatrix.sync.aligned.m8n8.x4.shared.b16 {%0,%1,%2,%3}, [%4];"
                 : "=r"(r[0]), "=r"(r[1]), "=r"(r[2]), "=r"(r[3]) : "r"(addr));
}
__device__ __forceinline__ void mma_bf16(float* c, const uint32_t* a,
                                         uint32_t b0, uint32_t b1) {
    asm volatile(
        "mma.sync.aligned.m16n8k16.row.col.f32.bf16.bf16.f32 "
        "{%0,%1,%2,%3}, {%4,%5,%6,%7}, {%8,%9}, {%0,%1,%2,%3};"
        : "+f"(c[0]), "+f"(c[1]), "+f"(c[2]), "+f"(c[3])
        : "r"(a[0]), "r"(a[1]), "r"(a[2]), "r"(a[3]), "r"(b0), "r"(b1));
}

// ---------------------------------------------------------------------------
// fp32 activation -> concatenated bf16 [hi | hi | lo], row stride KP
// ---------------------------------------------------------------------------
__global__ __launch_bounds__(256) void split_cat(
    const float* __restrict__ x, __nv_bfloat16* __restrict__ out, int n4)
{
    const int i = blockIdx.x * 256 + threadIdx.x;
    if (i >= n4) return;
    const float4 v = ((const float4*)x)[i];
    const int row = i >> 6;            // 64 float4 per 256-wide row
    const int c4  = (i & 63) << 2;
    __nv_bfloat16 h[4], l[4];
    const float f[4] = {v.x, v.y, v.z, v.w};
#pragma unroll
    for (int k = 0; k < 4; k++) {
        h[k] = __float2bfloat16(f[k]);
        l[k] = __float2bfloat16(f[k] - __bfloat162float(h[k]));
    }
    __nv_bfloat16* base = out + (size_t)row * KP + c4;
    *(uint2*)(base)       = *(const uint2*)h;
    *(uint2*)(base + 256) = *(const uint2*)h;
    *(uint2*)(base + 512) = *(const uint2*)l;
}

// Weight W[K=256,N] -> B't[N][KP] = [Wh(:,n) | Wl(:,n) | Wh(:,n)]
__global__ __launch_bounds__(256) void w_split_cat(
    const float* __restrict__ W, __nv_bfloat16* __restrict__ Bt, int N)
{
    const int idx = blockIdx.x * 256 + threadIdx.x;
    if (idx >= 256 * N) return;
    const int k = idx / N, n = idx % N;
    const float v = W[idx];
    const __nv_bfloat16 h = __float2bfloat16(v);
    const __nv_bfloat16 l = __float2bfloat16(v - __bfloat162float(h));
    __nv_bfloat16* base = Bt + (size_t)n * KP + k;
    base[0]   = h;
    base[256] = l;
    base[512] = h;
}

// ---------------------------------------------------------------------------
// bf16 mma.sync GEMM: C[M,N] = A'[M,KP] @ B't[N,KP]^T + bias (+ res)
// BM=128, BN=128, BK=32, 256 threads = 8 warps (4x2), warp tile 32x64.
// ---------------------------------------------------------------------------
__global__ __launch_bounds__(256) void gemm_mma(
    const __nv_bfloat16* __restrict__ A, const __nv_bfloat16* __restrict__ Bt,
    const float* __restrict__ bias, const float* __restrict__ res,
    float* __restrict__ C, int M, int N)
{
    __shared__ __align__(16) __nv_bfloat16 shA[2][ASZ];
    __shared__ __align__(16) __nv_bfloat16 shB[2][ASZ];

    const int tid  = threadIdx.x;
    const int lane = tid & 31;
    const int wid  = tid >> 5;
    const int wm   = wid & 3;          // 4 warps along M
    const int wn   = wid >> 2;         // 2 warps along N
    const int m0   = blockIdx.x * 128;
    const int n0   = blockIdx.y * 128;

    const uint32_t sA = smem_u32(shA[0]);
    const uint32_t sB = smem_u32(shB[0]);

    // ---- stage loaders: 512 16B-chunks per operand, 2 per thread ----
    auto load_stage = [&](int buf, int kt) {
        const int kbase = kt * BK;
#pragma unroll
        for (int it = 0; it < 2; it++) {
            const int c   = tid + it * 256;
            const int row = c >> 2;
            const int seg = (c & 3) << 3;          // bf16 elems
            const uint32_t soff = (uint32_t)(row * APAD + seg) * 2;
            // A (row clamp for the tail tile)
            const int ar = min(m0 + row, M - 1);
            cp_async16(sA + buf * (ASZ * 2) + soff,
                       A + (size_t)ar * KP + kbase + seg);
            // B
            cp_async16(sB + buf * (ASZ * 2) + soff,
                       Bt + (size_t)(n0 + row) * KP + kbase + seg);
        }
    };

    float acc[2][8][4];
#pragma unroll
    for (int mi = 0; mi < 2; mi++)
#pragma unroll
        for (int nj = 0; nj < 8; nj++)
#pragma unroll
            for (int k = 0; k < 4; k++) acc[mi][nj][k] = 0.f;

    load_stage(0, 0);
    cp_commit();

#pragma unroll 1
    for (int kt = 0; kt < NKIT; kt++) {
        if (kt + 1 < NKIT) {
            load_stage((kt + 1) & 1, kt + 1);
            cp_commit();
            cp_wait<1>();
        } else {
            cp_wait<0>();
        }
        __syncthreads();

        const int buf = kt & 1;
        const uint32_t aB = sA + buf * (ASZ * 2);
        const uint32_t bB = sB + buf * (ASZ * 2);

#pragma unroll
        for (int ks = 0; ks < 2; ks++) {
            // A fragments: 2 x ldmatrix.x4
            uint32_t afr[2][4];
#pragma unroll
            for (int mi = 0; mi < 2; mi++) {
                const int row = wm * 32 + mi * 16 + (lane & 15);
                const int col = ks * 16 + ((lane >> 4) << 3);
                ldmatrix_x4(afr[mi], aB + (uint32_t)(row * APAD + col) * 2);
            }
            // B fragments: 4 x ldmatrix.x4 (each covers two n8-tiles)
            uint32_t bfr[4][4];
#pragma unroll
            for (int njp = 0; njp < 4; njp++) {
                const int row = wn * 64 + njp * 16 + ((lane >> 4) & 1) * 8 + (lane & 7);
                const int col = ks * 16 + ((lane >> 3) & 1) * 8;
                ldmatrix_x4(bfr[njp], bB + (uint32_t)(row * APAD + col) * 2);
            }
#pragma unroll
            for (int mi = 0; mi < 2; mi++)
#pragma unroll
                for (int nj = 0; nj < 8; nj++)
                    mma_bf16(acc[mi][nj], afr[mi],
                             bfr[nj >> 1][(nj & 1) * 2],
                             bfr[nj >> 1][(nj & 1) * 2 + 1]);
        }
        __syncthreads();
    }

    // ---- epilogue ----
#pragma unroll
    for (int mi = 0; mi < 2; mi++) {
#pragma unroll
        for (int nj = 0; nj < 8; nj++) {
            const int col = n0 + wn * 64 + nj * 8 + (lane & 3) * 2;
            const int r0  = m0 + wm * 32 + mi * 16 + (lane >> 2);
            const int r1  = r0 + 8;
            const float b0 = bias[col], b1 = bias[col + 1];
            if (r0 < M) {
                float2 o = make_float2(acc[mi][nj][0] + b0, acc[mi][nj][1] + b1);
                if (res) {
                    const float2 rv = *(const float2*)(res + (size_t)r0 * N + col);
                    o.x += rv.x; o.y += rv.y;
                }
                *(float2*)(C + (size_t)r0 * N + col) = o;
            }
            if (r1 < M) {
                float2 o = make_float2(acc[mi][nj][2] + b0, acc[mi][nj][3] + b1);
                if (res) {
                    const float2 rv = *(const float2*)(res + (size_t)r1 * N + col);
                    o.x += rv.x; o.y += rv.y;
                }
                *(float2*)(C + (size_t)r1 * N + col) = o;
            }
        }
    }
}

// ---------------------------------------------------------------------------
// Sampler (round-2 design); emits TMP directly in concatenated bf16 layout.
// ---------------------------------------------------------------------------
__global__ __launch_bounds__(256) void msda_sample4(
    const float* __restrict__ V, const float* __restrict__ SO,
    const float* __restrict__ AWL, const float* __restrict__ refp,
    const int* __restrict__ shapes, const int* __restrict__ starts,
    __nv_bfloat16* __restrict__ outCat, int M)
{
    __shared__ int4   sOff[4][16][8];
    __shared__ float4 sW  [4][16][8];

    const int tid = threadIdx.x;

    // Phase A: precompute corner indices + (weights * softmax(aw))
    {
        const int wi  = tid << 1;
        const int bqL = wi >> 7;
        const int h   = (wi >> 4) & 7;
        const int pt0 = wi & 15;
        int bq = blockIdx.x * 4 + bqL;
        bq = min(bq, M - 1);

        const float2 lg = *(const float2*)(AWL + (size_t)bq * 128 + h * 16 + pt0);
        float mx = fmaxf(lg.x, lg.y);
#pragma unroll
        for (int off = 4; off; off >>= 1)
            mx = fmaxf(mx, __shfl_xor_sync(0xffffffffu, mx, off));
        const float e0 = expf(lg.x - mx);
        const float e1 = expf(lg.y - mx);
        float sm = e0 + e1;
#pragma unroll
        for (int off = 4; off; off >>= 1)
            sm += __shfl_xor_sync(0xffffffffu, sm, off);
        const float inv = 1.f / sm;

        const int l = pt0 >> 2;
        const int H = shapes[2 * l + 0];
        const int W = shapes[2 * l + 1];
        const int st = starts[l];
        const float2 rp = *(const float2*)(refp + ((size_t)bq * NLVL + l) * 2);
        const float4 so = *(const float4*)(SO + (size_t)bq * EDIM + h * 32 + pt0 * 2);

#pragma unroll
        for (int k = 0; k < 2; k++) {
            const int pt = pt0 + k;
            const float aw  = (k ? e1 : e0) * inv;
            const float sox = k ? so.z : so.x;
            const float soy = k ? so.w : so.y;

            const float x = fmaf(rp.x, (float)W, sox) - 0.5f;
            const float y = fmaf(rp.y, (float)H, soy) - 0.5f;
            const float xf = floorf(x), yf = floorf(y);
            const int x0 = (int)xf, y0 = (int)yf;
            const float wx1 = x - xf, wx0 = 1.f - wx1;
            const float wy1 = y - yf, wy0 = 1.f - wy1;

            const bool vx0 = (x0 >= 0) && (x0 < W);
            const bool vx1 = (x0 + 1 >= 0) && (x0 + 1 < W);
            const bool vy0 = (y0 >= 0) && (y0 < H);
            const bool vy1 = (y0 + 1 >= 0) && (y0 + 1 < H);

            const int cx0 = max(0, min(x0,     W - 1));
            const int cx1 = max(0, min(x0 + 1, W - 1));
            const int cy0 = max(0, min(y0,     H - 1));
            const int cy1 = max(0, min(y0 + 1, H - 1));

            int4 o;
            o.x = st + cy0 * W + cx0;
            o.y = st + cy0 * W + cx1;
            o.z = st + cy1 * W + cx0;
            o.w = st + cy1 * W + cx1;

            float4 w4;
            w4.x = (vx0 && vy0) ? wx0 * wy0 * aw : 0.f;
            w4.y = (vx1 && vy0) ? wx1 * wy0 * aw : 0.f;
            w4.z = (vx0 && vy1) ? wx0 * wy1 * aw : 0.f;
            w4.w = (vx1 && vy1) ? wx1 * wy1 * aw : 0.f;

            sOff[bqL][pt][h] = o;
            sW  [bqL][pt][h] = w4;
        }
    }
    __syncthreads();

    // Phase B: gather
    const int warpId = tid >> 5;
    const int lane   = tid & 31;
    const int bqL    = warpId >> 1;
    const int h      = ((warpId & 1) << 2) + (lane >> 3);
    const int c4     = lane & 7;
    const int bq     = blockIdx.x * 4 + bqL;
    if (bq >= M) return;
    const int b = bq / NQ;

    const float* vb = V + (size_t)b * NQ * EDIM + h * 32 + c4 * 4;

    float4 acc = make_float4(0.f, 0.f, 0.f, 0.f);
#pragma unroll
    for (int pt = 0; pt < 16; pt++) {
        const int4   o = sOff[bqL][pt][h];
        const float4 w = sW  [bqL][pt][h];

        const float4 v0 = *(const float4*)(vb + (size_t)o.x * EDIM);
        const float4 v1 = *(const float4*)(vb + (size_t)o.y * EDIM);
        const float4 v2 = *(const float4*)(vb + (size_t)o.z * EDIM);
        const float4 v3 = *(const float4*)(vb + (size_t)o.w * EDIM);

        acc.x = fmaf(w.x, v0.x, acc.x); acc.y = fmaf(w.x, v0.y, acc.y);
        acc.z = fmaf(w.x, v0.z, acc.z); acc.w = fmaf(w.x, v0.w, acc.w);
        acc.x = fmaf(w.y, v1.x, acc.x); acc.y = fmaf(w.y, v1.y, acc.y);
        acc.z = fmaf(w.y, v1.z, acc.z); acc.w = fmaf(w.y, v1.w, acc.w);
        acc.x = fmaf(w.z, v2.x, acc.x); acc.y = fmaf(w.z, v2.y, acc.y);
        acc.z = fmaf(w.z, v2.z, acc.z); acc.w = fmaf(w.z, v2.w, acc.w);
        acc.x = fmaf(w.w, v3.x, acc.x); acc.y = fmaf(w.w, v3.y, acc.y);
        acc.z = fmaf(w.w, v3.z, acc.z); acc.w = fmaf(w.w, v3.w, acc.w);
    }

    // split to concatenated bf16 [hi | hi | lo]
    __nv_bfloat16 hh[4], ll[4];
    const float f[4] = {acc.x, acc.y, acc.z, acc.w};
#pragma unroll
    for (int k = 0; k < 4; k++) {
        hh[k] = __float2bfloat16(f[k]);
        ll[k] = __float2bfloat16(f[k] - __bfloat162float(hh[k]));
    }
    __nv_bfloat16* base = outCat + (size_t)bq * KP + h * 32 + c4 * 4;
    *(uint2*)(base)       = *(const uint2*)hh;
    *(uint2*)(base + 256) = *(const uint2*)hh;
    *(uint2*)(base + 512) = *(const uint2*)ll;
}

// ---------------------------------------------------------------------------
// Launch
// ---------------------------------------------------------------------------
extern "C" void kernel_launch(void* const* d_in, const int* in_sizes, int n_in,
                              void* d_out, int out_size)
{
    const float* query  = (const float*)d_in[0];
    const float* value  = (const float*)d_in[1];
    const float* refp   = (const float*)d_in[2];
    const int*   shapes = (const int*)  d_in[3];
    const int*   starts = (const int*)  d_in[4];
    const float* Wv  = (const float*)d_in[5];
    const float* bv  = (const float*)d_in[6];
    const float* Wso = (const float*)d_in[7];
    const float* bso = (const float*)d_in[8];
    const float* Waw = (const float*)d_in[9];
    const float* baw = (const float*)d_in[10];
    const float* Wo  = (const float*)d_in[11];
    const float* bo  = (const float*)d_in[12];
    float* out = (float*)d_out;

    const int M = in_sizes[0] / EDIM;   // 40394

    float *pV, *pSO, *pAWL;
    __nv_bfloat16 *pAval, *pAq, *pAtmp, *pBv, *pBso, *pBaw, *pBo;
    cudaGetSymbolAddress((void**)&pV,    g_V);
    cudaGetSymbolAddress((void**)&pSO,   g_SO);
    cudaGetSymbolAddress((void**)&pAWL,  g_AWL);
    cudaGetSymbolAddress((void**)&pAval, g_Aval);
    cudaGetSymbolAddress((void**)&pAq,   g_Aq);
    cudaGetSymbolAddress((void**)&pAtmp, g_Atmp);
    cudaGetSymbolAddress((void**)&pBv,   g_Bv);
    cudaGetSymbolAddress((void**)&pBso,  g_Bso);
    cudaGetSymbolAddress((void**)&pBaw,  g_Baw);
    cudaGetSymbolAddress((void**)&pBo,   g_Bo);

    const int n4 = M * (EDIM / 4);
    const int cvtBlocks = (n4 + 255) / 256;
    const int mTiles = (M + 127) / 128;
    const dim3 g256(mTiles, 2);
    const dim3 g128(mTiles, 1);

    // conversions
    split_cat<<<cvtBlocks, 256>>>(value, pAval, n4);
    split_cat<<<cvtBlocks, 256>>>(query, pAq,   n4);
    w_split_cat<<<(256 * 256 + 255) / 256, 256>>>(Wv,  pBv,  256);
    w_split_cat<<<(256 * 256 + 255) / 256, 256>>>(Wso, pBso, 256);
    w_split_cat<<<(256 * 128 + 255) / 256, 256>>>(Waw, pBaw, 128);
    w_split_cat<<<(256 * 256 + 255) / 256, 256>>>(Wo,  pBo,  256);

    // GEMMs + sampler
    gemm_mma<<<g256, 256>>>(pAval, pBv,  bv,  nullptr, pV,   M, 256);
    gemm_mma<<<g256, 256>>>(pAq,   pBso, bso, nullptr, pSO,  M, 256);
    gemm_mma<<<g128, 256>>>(pAq,   pBaw, baw, nullptr, pAWL, M, 128);
    msda_sample4<<<(M + 3) / 4, 256>>>(pV, pSO, pAWL, refp, shapes, starts, pAtmp, M);
    gemm_mma<<<g256, 256>>>(pAtmp, pBo,  bo,  query,   out,  M, 256);
}

// round 5
// speedup vs baseline: 2.3728x; 1.0640x over previous
#include <cuda_runtime.h>
#include <cuda_bf16.h>
#include <math.h>
#include <stdint.h>

// ---------------------------------------------------------------------------
// MultiScaleDeformableAttention, fp32 in/out.
// GEMMs via mma.sync bf16 (m16n8k16), 3-term error compensation as a single
// K=768 GEMM:  A' = [Ah|Ah|Al],  B't = [Bh|Bl|Bh].
// Round-5: fused SO+AW GEMM (N=384), merged weight prep, 3-stage cp.async.
// ---------------------------------------------------------------------------

#define NQ    20197
#define BSZ   2
#define EDIM  256
#define NLVL  4
#define MTOT  (BSZ * NQ)     // 40394

#define KP    768            // concatenated K
#define BK    32
#define NKIT  (KP / BK)      // 24
#define APAD  40             // smem row elems (80B) -> conflict-free ldmatrix
#define ASZ   (128 * APAD)   // elems per stage per operand
#define STAGE_B (2 * ASZ * 2)      // bytes per stage (A + B)
#define SMEM_GEMM (3 * STAGE_B)    // 61440 B dynamic smem

#define QASTR 384            // fused SO|AW row stride

// ------------------------------- scratch ------------------------------------
__device__ float g_V  [MTOT * EDIM];
__device__ float g_QA [(size_t)MTOT * QASTR];   // [SO(256) | AWL(128)]
__device__ __nv_bfloat16 g_Aval[(size_t)MTOT * KP];
__device__ __nv_bfloat16 g_Aq  [(size_t)MTOT * KP];
__device__ __nv_bfloat16 g_Atmp[(size_t)MTOT * KP];
__device__ __nv_bfloat16 g_Bv [256 * KP];
__device__ __nv_bfloat16 g_Bqa[QASTR * KP];
__device__ __nv_bfloat16 g_Bo [256 * KP];
__device__ float g_biasQA[QASTR];

// -------------------------- small PTX helpers -------------------------------
__device__ __forceinline__ uint32_t smem_u32(const void* p) {
    uint32_t a;
    asm("{ .reg .u64 t; cvta.to.shared.u64 t, %1; cvt.u32.u64 %0, t; }"
        : "=r"(a) : "l"(p));
    return a;
}
__device__ __forceinline__ void cp_async16(uint32_t dst, const void* src) {
    asm volatile("cp.async.cg.shared.global [%0], [%1], 16;"
                 :: "r"(dst), "l"(src) : "memory");
}
__device__ __forceinline__ void cp_commit() {
    asm volatile("cp.async.commit_group;" ::: "memory");
}
template <int N>
__device__ __forceinline__ void cp_wait() {
    asm volatile("cp.async.wait_group %0;" :: "n"(N) : "memory");
}
__device__ __forceinline__ void ldmatrix_x4(uint32_t* r, uint32_t addr) {
    asm volatile("ldmatrix.sync.aligned.m8n8.x4.shared.b16 {%0,%1,%2,%3}, [%4];"
                 : "=r"(r[0]), "=r"(r[1]), "=r"(r[2]), "=r"(r[3]) : "r"(addr));
}
__device__ __forceinline__ void mma_bf16(float* c, const uint32_t* a,
                                         uint32_t b0, uint32_t b1) {
    asm volatile(
        "mma.sync.aligned.m16n8k16.row.col.f32.bf16.bf16.f32 "
        "{%0,%1,%2,%3}, {%4,%5,%6,%7}, {%8,%9}, {%0,%1,%2,%3};"
        : "+f"(c[0]), "+f"(c[1]), "+f"(c[2]), "+f"(c[3])
        : "r"(a[0]), "r"(a[1]), "r"(a[2]), "r"(a[3]), "r"(b0), "r"(b1));
}

// ---------------------------------------------------------------------------
// fp32 activation -> concatenated bf16 [hi | hi | lo], row stride KP
// ---------------------------------------------------------------------------
__global__ __launch_bounds__(256) void split_cat(
    const float* __restrict__ x, __nv_bfloat16* __restrict__ out, int n4)
{
    const int i = blockIdx.x * 256 + threadIdx.x;
    if (i >= n4) return;
    const float4 v = ((const float4*)x)[i];
    const int row = i >> 6;
    const int c4  = (i & 63) << 2;
    __nv_bfloat16 h[4], l[4];
    const float f[4] = {v.x, v.y, v.z, v.w};
#pragma unroll
    for (int k = 0; k < 4; k++) {
        h[k] = __float2bfloat16(f[k]);
        l[k] = __float2bfloat16(f[k] - __bfloat162float(h[k]));
    }
    __nv_bfloat16* base = out + (size_t)row * KP + c4;
    *(uint2*)(base)       = *(const uint2*)h;
    *(uint2*)(base + 256) = *(const uint2*)h;
    *(uint2*)(base + 512) = *(const uint2*)l;
}

// ---------------------------------------------------------------------------
// One-shot weight prep: all W -> B't[N][KP]=[h|l|h] transposed splits + bias cat.
//   idx ranges: [0,65536) Wv -> Bv | [65536,131072) Wso -> Bqa[0:256)
//   [131072,163840) Waw -> Bqa[256:384) | [163840,229376) Wo -> Bo
//   [229376,229760) bias concat
// ---------------------------------------------------------------------------
__global__ __launch_bounds__(256) void prep_weights(
    const float* __restrict__ Wv,  const float* __restrict__ Wso,
    const float* __restrict__ Waw, const float* __restrict__ Wo,
    const float* __restrict__ bso, const float* __restrict__ baw)
{
    const int idx = blockIdx.x * 256 + threadIdx.x;
    const float* W;
    __nv_bfloat16* Bt;
    int li, N, nofs = 0;
    if (idx < 65536)        { W = Wv;  Bt = g_Bv;  li = idx;          N = 256; }
    else if (idx < 131072)  { W = Wso; Bt = g_Bqa; li = idx - 65536;  N = 256; }
    else if (idx < 163840)  { W = Waw; Bt = g_Bqa; li = idx - 131072; N = 128; nofs = 256; }
    else if (idx < 229376)  { W = Wo;  Bt = g_Bo;  li = idx - 163840; N = 256; }
    else {
        const int i = idx - 229376;
        if (i < 256)      g_biasQA[i] = bso[i];
        else if (i < 384) g_biasQA[i] = baw[i - 256];
        return;
    }
    const int k = li / N, n = li % N;
    const float v = W[li];
    const __nv_bfloat16 h = __float2bfloat16(v);
    const __nv_bfloat16 l = __float2bfloat16(v - __bfloat162float(h));
    __nv_bfloat16* base = Bt + (size_t)(n + nofs) * KP + k;
    base[0]   = h;
    base[256] = l;
    base[512] = h;
}

// ---------------------------------------------------------------------------
// bf16 mma.sync GEMM: C[M,N] = A'[M,KP] @ B't[N,KP]^T + bias (+ res)
// BM=128, BN=128, BK=32, 8 warps (4x2), warp tile 32x64.
// 3-stage cp.async pipeline, one __syncthreads per k-iter.
// ---------------------------------------------------------------------------
__global__ __launch_bounds__(256) void gemm_mma(
    const __nv_bfloat16* __restrict__ A, const __nv_bfloat16* __restrict__ Bt,
    const float* __restrict__ bias, const float* __restrict__ res,
    float* __restrict__ C, int M, int N)
{
    extern __shared__ __align__(16) char smem[];
    const uint32_t sBase = smem_u32(smem);

    const int tid  = threadIdx.x;
    const int lane = tid & 31;
    const int wid  = tid >> 5;
    const int wm   = wid & 3;
    const int wn   = wid >> 2;
    const int m0   = blockIdx.x * 128;
    const int n0   = blockIdx.y * 128;

    // per-thread load coords (2 chunks of 16B per operand per stage)
    auto load_stage = [&](int stg, int kt) {
        const int kbase = kt * BK;
        const uint32_t sA = sBase + (uint32_t)stg * STAGE_B;
        const uint32_t sB = sA + ASZ * 2;
#pragma unroll
        for (int it = 0; it < 2; it++) {
            const int c   = tid + it * 256;
            const int row = c >> 2;
            const int seg = (c & 3) << 3;
            const uint32_t soff = (uint32_t)(row * APAD + seg) * 2;
            const int ar = min(m0 + row, M - 1);
            cp_async16(sA + soff, A + (size_t)ar * KP + kbase + seg);
            cp_async16(sB + soff, Bt + (size_t)(n0 + row) * KP + kbase + seg);
        }
    };

    float acc[2][8][4];
#pragma unroll
    for (int mi = 0; mi < 2; mi++)
#pragma unroll
        for (int nj = 0; nj < 8; nj++)
#pragma unroll
            for (int k = 0; k < 4; k++) acc[mi][nj][k] = 0.f;

    load_stage(0, 0); cp_commit();
    load_stage(1, 1); cp_commit();

    int stg = 0;
#pragma unroll 1
    for (int kt = 0; kt < NKIT; kt++) {
        cp_wait<1>();
        __syncthreads();

        // issue loads for kt+2 (overwrites buffer consumed at kt-1)
        if (kt + 2 < NKIT) load_stage((stg + 2) % 3, kt + 2);
        cp_commit();   // empty groups at tail keep wait<1> accounting exact

        const uint32_t aB = sBase + (uint32_t)stg * STAGE_B;
        const uint32_t bB = aB + ASZ * 2;

#pragma unroll
        for (int ks = 0; ks < 2; ks++) {
            uint32_t afr[2][4];
#pragma unroll
            for (int mi = 0; mi < 2; mi++) {
                const int row = wm * 32 + mi * 16 + (lane & 15);
                const int col = ks * 16 + ((lane >> 4) << 3);
                ldmatrix_x4(afr[mi], aB + (uint32_t)(row * APAD + col) * 2);
            }
            uint32_t bfr[4][4];
#pragma unroll
            for (int njp = 0; njp < 4; njp++) {
                const int row = wn * 64 + njp * 16 + ((lane >> 4) & 1) * 8 + (lane & 7);
                const int col = ks * 16 + ((lane >> 3) & 1) * 8;
                ldmatrix_x4(bfr[njp], bB + (uint32_t)(row * APAD + col) * 2);
            }
#pragma unroll
            for (int mi = 0; mi < 2; mi++)
#pragma unroll
                for (int nj = 0; nj < 8; nj++)
                    mma_bf16(acc[mi][nj], afr[mi],
                             bfr[nj >> 1][(nj & 1) * 2],
                             bfr[nj >> 1][(nj & 1) * 2 + 1]);
        }
        stg = (stg + 1) % 3;
    }

    // ---- epilogue ----
#pragma unroll
    for (int mi = 0; mi < 2; mi++) {
#pragma unroll
        for (int nj = 0; nj < 8; nj++) {
            const int col = n0 + wn * 64 + nj * 8 + (lane & 3) * 2;
            const int r0  = m0 + wm * 32 + mi * 16 + (lane >> 2);
            const int r1  = r0 + 8;
            const float b0 = bias[col], b1 = bias[col + 1];
            if (r0 < M) {
                float2 o = make_float2(acc[mi][nj][0] + b0, acc[mi][nj][1] + b1);
                if (res) {
                    const float2 rv = *(const float2*)(res + (size_t)r0 * N + col);
                    o.x += rv.x; o.y += rv.y;
                }
                *(float2*)(C + (size_t)r0 * N + col) = o;
            }
            if (r1 < M) {
                float2 o = make_float2(acc[mi][nj][2] + b0, acc[mi][nj][3] + b1);
                if (res) {
                    const float2 rv = *(const float2*)(res + (size_t)r1 * N + col);
                    o.x += rv.x; o.y += rv.y;
                }
                *(float2*)(C + (size_t)r1 * N + col) = o;
            }
        }
    }
}

// ---------------------------------------------------------------------------
// Sampler; reads SO/AWL from fused QA buffer (stride 384), emits bf16 cat TMP.
// ---------------------------------------------------------------------------
__global__ __launch_bounds__(256) void msda_sample4(
    const float* __restrict__ V, const float* __restrict__ QA,
    const float* __restrict__ refp,
    const int* __restrict__ shapes, const int* __restrict__ starts,
    __nv_bfloat16* __restrict__ outCat, int M)
{
    __shared__ int4   sOff[4][16][8];
    __shared__ float4 sW  [4][16][8];

    const int tid = threadIdx.x;

    // Phase A
    {
        const int wi  = tid << 1;
        const int bqL = wi >> 7;
        const int h   = (wi >> 4) & 7;
        const int pt0 = wi & 15;
        int bq = blockIdx.x * 4 + bqL;
        bq = min(bq, M - 1);

        const float2 lg = *(const float2*)(QA + (size_t)bq * QASTR + 256 + h * 16 + pt0);
        float mx = fmaxf(lg.x, lg.y);
#pragma unroll
        for (int off = 4; off; off >>= 1)
            mx = fmaxf(mx, __shfl_xor_sync(0xffffffffu, mx, off));
        const float e0 = expf(lg.x - mx);
        const float e1 = expf(lg.y - mx);
        float sm = e0 + e1;
#pragma unroll
        for (int off = 4; off; off >>= 1)
            sm += __shfl_xor_sync(0xffffffffu, sm, off);
        const float inv = 1.f / sm;

        const int l = pt0 >> 2;
        const int H = shapes[2 * l + 0];
        const int W = shapes[2 * l + 1];
        const int st = starts[l];
        const float2 rp = *(const float2*)(refp + ((size_t)bq * NLVL + l) * 2);
        const float4 so = *(const float4*)(QA + (size_t)bq * QASTR + h * 32 + pt0 * 2);

#pragma unroll
        for (int k = 0; k < 2; k++) {
            const int pt = pt0 + k;
            const float aw  = (k ? e1 : e0) * inv;
            const float sox = k ? so.z : so.x;
            const float soy = k ? so.w : so.y;

            const float x = fmaf(rp.x, (float)W, sox) - 0.5f;
            const float y = fmaf(rp.y, (float)H, soy) - 0.5f;
            const float xf = floorf(x), yf = floorf(y);
            const int x0 = (int)xf, y0 = (int)yf;
            const float wx1 = x - xf, wx0 = 1.f - wx1;
            const float wy1 = y - yf, wy0 = 1.f - wy1;

            const bool vx0 = (x0 >= 0) && (x0 < W);
            const bool vx1 = (x0 + 1 >= 0) && (x0 + 1 < W);
            const bool vy0 = (y0 >= 0) && (y0 < H);
            const bool vy1 = (y0 + 1 >= 0) && (y0 + 1 < H);

            const int cx0 = max(0, min(x0,     W - 1));
            const int cx1 = max(0, min(x0 + 1, W - 1));
            const int cy0 = max(0, min(y0,     H - 1));
            const int cy1 = max(0, min(y0 + 1, H - 1));

            int4 o;
            o.x = st + cy0 * W + cx0;
            o.y = st + cy0 * W + cx1;
            o.z = st + cy1 * W + cx0;
            o.w = st + cy1 * W + cx1;

            float4 w4;
            w4.x = (vx0 && vy0) ? wx0 * wy0 * aw : 0.f;
            w4.y = (vx1 && vy0) ? wx1 * wy0 * aw : 0.f;
            w4.z = (vx0 && vy1) ? wx0 * wy1 * aw : 0.f;
            w4.w = (vx1 && vy1) ? wx1 * wy1 * aw : 0.f;

            sOff[bqL][pt][h] = o;
            sW  [bqL][pt][h] = w4;
        }
    }
    __syncthreads();

    // Phase B
    const int warpId = tid >> 5;
    const int lane   = tid & 31;
    const int bqL    = warpId >> 1;
    const int h      = ((warpId & 1) << 2) + (lane >> 3);
    const int c4     = lane & 7;
    const int bq     = blockIdx.x * 4 + bqL;
    if (bq >= M) return;
    const int b = bq / NQ;

    const float* vb = V + (size_t)b * NQ * EDIM + h * 32 + c4 * 4;

    float4 acc = make_float4(0.f, 0.f, 0.f, 0.f);
#pragma unroll
    for (int pt = 0; pt < 16; pt++) {
        const int4   o = sOff[bqL][pt][h];
        const float4 w = sW  [bqL][pt][h];

        const float4 v0 = *(const float4*)(vb + (size_t)o.x * EDIM);
        const float4 v1 = *(const float4*)(vb + (size_t)o.y * EDIM);
        const float4 v2 = *(const float4*)(vb + (size_t)o.z * EDIM);
        const float4 v3 = *(const float4*)(vb + (size_t)o.w * EDIM);

        acc.x = fmaf(w.x, v0.x, acc.x); acc.y = fmaf(w.x, v0.y, acc.y);
        acc.z = fmaf(w.x, v0.z, acc.z); acc.w = fmaf(w.x, v0.w, acc.w);
        acc.x = fmaf(w.y, v1.x, acc.x); acc.y = fmaf(w.y, v1.y, acc.y);
        acc.z = fmaf(w.y, v1.z, acc.z); acc.w = fmaf(w.y, v1.w, acc.w);
        acc.x = fmaf(w.z, v2.x, acc.x); acc.y = fmaf(w.z, v2.y, acc.y);
        acc.z = fmaf(w.z, v2.z, acc.z); acc.w = fmaf(w.z, v2.w, acc.w);
        acc.x = fmaf(w.w, v3.x, acc.x); acc.y = fmaf(w.w, v3.y, acc.y);
        acc.z = fmaf(w.w, v3.z, acc.z); acc.w = fmaf(w.w, v3.w, acc.w);
    }

    __nv_bfloat16 hh[4], ll[4];
    const float f[4] = {acc.x, acc.y, acc.z, acc.w};
#pragma unroll
    for (int k = 0; k < 4; k++) {
        hh[k] = __float2bfloat16(f[k]);
        ll[k] = __float2bfloat16(f[k] - __bfloat162float(hh[k]));
    }
    __nv_bfloat16* base = outCat + (size_t)bq * KP + h * 32 + c4 * 4;
    *(uint2*)(base)       = *(const uint2*)hh;
    *(uint2*)(base + 256) = *(const uint2*)hh;
    *(uint2*)(base + 512) = *(const uint2*)ll;
}

// ---------------------------------------------------------------------------
// Launch
// ---------------------------------------------------------------------------
extern "C" void kernel_launch(void* const* d_in, const int* in_sizes, int n_in,
                              void* d_out, int out_size)
{
    const float* query  = (const float*)d_in[0];
    const float* value  = (const float*)d_in[1];
    const float* refp   = (const float*)d_in[2];
    const int*   shapes = (const int*)  d_in[3];
    const int*   starts = (const int*)  d_in[4];
    const float* Wv  = (const float*)d_in[5];
    const float* bv  = (const float*)d_in[6];
    const float* Wso = (const float*)d_in[7];
    const float* Waw = (const float*)d_in[9];
    const float* baw = (const float*)d_in[10];
    const float* Wo  = (const float*)d_in[11];
    const float* bo  = (const float*)d_in[12];
    const float* bso = (const float*)d_in[8];
    float* out = (float*)d_out;

    const int M = in_sizes[0] / EDIM;   // 40394

    float *pV, *pQA, *pBiasQA;
    __nv_bfloat16 *pAval, *pAq, *pAtmp, *pBv, *pBqa, *pBo;
    cudaGetSymbolAddress((void**)&pV,     g_V);
    cudaGetSymbolAddress((void**)&pQA,    g_QA);
    cudaGetSymbolAddress((void**)&pBiasQA,g_biasQA);
    cudaGetSymbolAddress((void**)&pAval,  g_Aval);
    cudaGetSymbolAddress((void**)&pAq,    g_Aq);
    cudaGetSymbolAddress((void**)&pAtmp,  g_Atmp);
    cudaGetSymbolAddress((void**)&pBv,    g_Bv);
    cudaGetSymbolAddress((void**)&pBqa,   g_Bqa);
    cudaGetSymbolAddress((void**)&pBo,    g_Bo);

    cudaFuncSetAttribute(gemm_mma, cudaFuncAttributeMaxDynamicSharedMemorySize, SMEM_GEMM);

    const int n4 = M * (EDIM / 4);
    const int cvtBlocks = (n4 + 255) / 256;
    const int mTiles = (M + 127) / 128;
    const dim3 g256(mTiles, 2);
    const dim3 g384(mTiles, 3);

    // conversions (one merged weight-prep launch)
    split_cat<<<cvtBlocks, 256>>>(value, pAval, n4);
    split_cat<<<cvtBlocks, 256>>>(query, pAq,   n4);
    prep_weights<<<(229760 + 255) / 256, 256>>>(Wv, Wso, Waw, Wo, bso, baw);

    // GEMMs + sampler
    gemm_mma<<<g256, 256, SMEM_GEMM>>>(pAval, pBv,  bv,      nullptr, pV,  M, 256);
    gemm_mma<<<g384, 256, SMEM_GEMM>>>(pAq,   pBqa, pBiasQA, nullptr, pQA, M, QASTR);
    msda_sample4<<<(M + 3) / 4, 256>>>(pV, pQA, refp, shapes, starts, pAtmp, M);
    gemm_mma<<<g256, 256, SMEM_GEMM>>>(pAtmp, pBo,  bo,      query,   out, M, 256);
}

// round 6
// speedup vs baseline: 2.6299x; 1.1083x over previous
#include <cuda_runtime.h>
#include <cuda_bf16.h>
#include <math.h>
#include <stdint.h>

// ---------------------------------------------------------------------------
// MultiScaleDeformableAttention, fp32 in/out.
// GEMMs: mma.sync bf16 m16n8k16, 3-term compensation with REGISTER reuse:
//   A' = [Ah|Al] (K=512), B't = [Bh|Bl];  per k16: acc += Ah*Bh + Ah*Bl + Al*Bh
// Round-6: removes the duplicated-Ah/Bh streaming of the K=768 layout
// (-33% smem + global GEMM traffic), 2 CTAs/SM, 3-stage cp.async.
// ---------------------------------------------------------------------------

#define NQ    20197
#define BSZ   2
#define EDIM  256
#define NLVL  4
#define MTOT  (BSZ * NQ)     // 40394

#define KP2   512            // [hi(256) | lo(256)] row stride
#define BK    32
#define NKIT  8              // 256 / BK
#define APAD2 72             // stage row elems (64 data + 8 pad)
#define TILE_E (128 * APAD2) // elems per operand per stage
#define STAGE_B (2 * TILE_E * 2)     // bytes per stage (A + B) = 36864
#define SMEM_GEMM (3 * STAGE_B)      // 110592 B

#define QASTR 384            // fused SO|AW output row stride

// ------------------------------- scratch ------------------------------------
__device__ float g_V  [MTOT * EDIM];
__device__ float g_QA [(size_t)MTOT * QASTR];   // [SO(256) | AWL(128)]
__device__ __nv_bfloat16 g_Aval[(size_t)MTOT * KP2];
__device__ __nv_bfloat16 g_Aq  [(size_t)MTOT * KP2];
__device__ __nv_bfloat16 g_Atmp[(size_t)MTOT * KP2];
__device__ __nv_bfloat16 g_Bv [256 * KP2];
__device__ __nv_bfloat16 g_Bqa[QASTR * KP2];
__device__ __nv_bfloat16 g_Bo [256 * KP2];
__device__ float g_biasQA[QASTR];

// -------------------------- small PTX helpers -------------------------------
__device__ __forceinline__ uint32_t smem_u32(const void* p) {
    uint32_t a;
    asm("{ .reg .u64 t; cvta.to.shared.u64 t, %1; cvt.u32.u64 %0, t; }"
        : "=r"(a) : "l"(p));
    return a;
}
__device__ __forceinline__ void cp_async16(uint32_t dst, const void* src) {
    asm volatile("cp.async.cg.shared.global [%0], [%1], 16;"
                 :: "r"(dst), "l"(src) : "memory");
}
__device__ __forceinline__ void cp_commit() {
    asm volatile("cp.async.commit_group;" ::: "memory");
}
template <int N>
__device__ __forceinline__ void cp_wait() {
    asm volatile("cp.async.wait_group %0;" :: "n"(N) : "memory");
}
__device__ __forceinline__ void ldmatrix_x4(uint32_t* r, uint32_t addr) {
    asm volatile("ldmatrix.sync.aligned.m8n8.x4.shared.b16 {%0,%1,%2,%3}, [%4];"
                 : "=r"(r[0]), "=r"(r[1]), "=r"(r[2]), "=r"(r[3]) : "r"(addr));
}
__device__ __forceinline__ void mma_bf16(float* c, const uint32_t* a,
                                         uint32_t b0, uint32_t b1) {
    asm volatile(
        "mma.sync.aligned.m16n8k16.row.col.f32.bf16.bf16.f32 "
        "{%0,%1,%2,%3}, {%4,%5,%6,%7}, {%8,%9}, {%0,%1,%2,%3};"
        : "+f"(c[0]), "+f"(c[1]), "+f"(c[2]), "+f"(c[3])
        : "r"(a[0]), "r"(a[1]), "r"(a[2]), "r"(a[3]), "r"(b0), "r"(b1));
}

// ---------------------------------------------------------------------------
// fp32 activation -> bf16 [hi(256) | lo(256)], row stride KP2
// ---------------------------------------------------------------------------
__global__ __launch_bounds__(256) void split_cat(
    const float* __restrict__ x, __nv_bfloat16* __restrict__ out, int n4)
{
    const int i = blockIdx.x * 256 + threadIdx.x;
    if (i >= n4) return;
    const float4 v = ((const float4*)x)[i];
    const int row = i >> 6;
    const int c4  = (i & 63) << 2;
    __nv_bfloat16 h[4], l[4];
    const float f[4] = {v.x, v.y, v.z, v.w};
#pragma unroll
    for (int k = 0; k < 4; k++) {
        h[k] = __float2bfloat16(f[k]);
        l[k] = __float2bfloat16(f[k] - __bfloat162float(h[k]));
    }
    __nv_bfloat16* base = out + (size_t)row * KP2 + c4;
    *(uint2*)(base)       = *(const uint2*)h;
    *(uint2*)(base + 256) = *(const uint2*)l;
}

// ---------------------------------------------------------------------------
// One-shot weight prep: W[K=256,N] -> B't[N][KP2]=[h|l] transposed + bias cat.
// ---------------------------------------------------------------------------
__global__ __launch_bounds__(256) void prep_weights(
    const float* __restrict__ Wv,  const float* __restrict__ Wso,
    const float* __restrict__ Waw, const float* __restrict__ Wo,
    const float* __restrict__ bso, const float* __restrict__ baw)
{
    const int idx = blockIdx.x * 256 + threadIdx.x;
    const float* W;
    __nv_bfloat16* Bt;
    int li, N, nofs = 0;
    if (idx < 65536)        { W = Wv;  Bt = g_Bv;  li = idx;          N = 256; }
    else if (idx < 131072)  { W = Wso; Bt = g_Bqa; li = idx - 65536;  N = 256; }
    else if (idx < 163840)  { W = Waw; Bt = g_Bqa; li = idx - 131072; N = 128; nofs = 256; }
    else if (idx < 229376)  { W = Wo;  Bt = g_Bo;  li = idx - 163840; N = 256; }
    else {
        const int i = idx - 229376;
        if (i < 256)      g_biasQA[i] = bso[i];
        else if (i < 384) g_biasQA[i] = baw[i - 256];
        return;
    }
    const int k = li / N, n = li % N;
    const float v = W[li];
    const __nv_bfloat16 h = __float2bfloat16(v);
    const __nv_bfloat16 l = __float2bfloat16(v - __bfloat162float(h));
    __nv_bfloat16* base = Bt + (size_t)(n + nofs) * KP2 + k;
    base[0]   = h;
    base[256] = l;
}

// ---------------------------------------------------------------------------
// bf16 mma GEMM with register-reuse 3-term compensation.
// C[M,N] = (Ah+Al)[M,256] @ (Bh+Bl)[N,256]^T + bias (+ res)
// BM=128, BN=128, BK=32 (stage holds h+l: rows of 64 elems, pad to 72).
// 8 warps (4x2), warp tile 32x64. 3-stage cp.async, 2 CTAs/SM.
// ---------------------------------------------------------------------------
__global__ __launch_bounds__(256, 2) void gemm_mma(
    const __nv_bfloat16* __restrict__ A, const __nv_bfloat16* __restrict__ Bt,
    const float* __restrict__ bias, const float* __restrict__ res,
    float* __restrict__ C, int M, int N)
{
    extern __shared__ __align__(16) char smem[];
    const uint32_t sBase = smem_u32(smem);

    const int tid  = threadIdx.x;
    const int lane = tid & 31;
    const int wid  = tid >> 5;
    const int wm   = wid & 3;
    const int wn   = wid >> 2;
    const int m0   = blockIdx.x * 128;
    const int n0   = blockIdx.y * 128;

    // stage: A tile 128 rows x [h(32)|l(32)] elems (pad 72), then B tile same.
    auto load_stage = [&](int stg, int kt) {
        const int kbase = kt * BK;
        const uint32_t sA = sBase + (uint32_t)stg * STAGE_B;
        const uint32_t sB = sA + TILE_E * 2;
#pragma unroll
        for (int it = 0; it < 4; it++) {
            const int c   = tid + it * 256;          // 0..1023
            const int row = c >> 3;
            const int seg = (c & 7) << 3;            // 0,8,...,56 elems
            const int gcol = (seg < 32) ? (kbase + seg) : (256 + kbase + seg - 32);
            const uint32_t soff = (uint32_t)(row * APAD2 + seg) * 2;
            const int ar = min(m0 + row, M - 1);
            cp_async16(sA + soff, A + (size_t)ar * KP2 + gcol);
            cp_async16(sB + soff, Bt + (size_t)(n0 + row) * KP2 + gcol);
        }
    };

    float acc[2][8][4];
#pragma unroll
    for (int mi = 0; mi < 2; mi++)
#pragma unroll
        for (int nj = 0; nj < 8; nj++)
#pragma unroll
            for (int k = 0; k < 4; k++) acc[mi][nj][k] = 0.f;

    load_stage(0, 0); cp_commit();
    load_stage(1, 1); cp_commit();

    int stg = 0;
#pragma unroll 1
    for (int kt = 0; kt < NKIT; kt++) {
        cp_wait<1>();
        __syncthreads();

        if (kt + 2 < NKIT) load_stage((stg + 2) % 3, kt + 2);
        cp_commit();   // empty groups at tail keep wait<1> exact

        const uint32_t aB = sBase + (uint32_t)stg * STAGE_B;
        const uint32_t bB = aB + TILE_E * 2;

#pragma unroll
        for (int ks = 0; ks < 2; ks++) {
            // A fragments: hi and lo, 2 m16 tiles each
            uint32_t ah[2][4], al[2][4];
#pragma unroll
            for (int mi = 0; mi < 2; mi++) {
                const int row = wm * 32 + mi * 16 + (lane & 15);
                const int col = ks * 16 + ((lane >> 4) << 3);
                ldmatrix_x4(ah[mi], aB + (uint32_t)(row * APAD2 + col) * 2);
                ldmatrix_x4(al[mi], aB + (uint32_t)(row * APAD2 + 32 + col) * 2);
            }
#pragma unroll
            for (int njp = 0; njp < 4; njp++) {
                const int row = wn * 64 + njp * 16 + ((lane >> 4) & 1) * 8 + (lane & 7);
                const int col = ks * 16 + ((lane >> 3) & 1) * 8;
                uint32_t bh[4], bl[4];
                ldmatrix_x4(bh, bB + (uint32_t)(row * APAD2 + col) * 2);
                ldmatrix_x4(bl, bB + (uint32_t)(row * APAD2 + 32 + col) * 2);
#pragma unroll
                for (int mi = 0; mi < 2; mi++) {
                    float* a0 = acc[mi][njp * 2];
                    float* a1 = acc[mi][njp * 2 + 1];
                    mma_bf16(a0, ah[mi], bh[0], bh[1]);   // Ah*Bh
                    mma_bf16(a1, ah[mi], bh[2], bh[3]);
                    mma_bf16(a0, ah[mi], bl[0], bl[1]);   // Ah*Bl
                    mma_bf16(a1, ah[mi], bl[2], bl[3]);
                    mma_bf16(a0, al[mi], bh[0], bh[1]);   // Al*Bh
                    mma_bf16(a1, al[mi], bh[2], bh[3]);
                }
            }
        }
        stg = (stg + 1) % 3;
    }

    // ---- epilogue ----
#pragma unroll
    for (int mi = 0; mi < 2; mi++) {
#pragma unroll
        for (int nj = 0; nj < 8; nj++) {
            const int col = n0 + wn * 64 + nj * 8 + (lane & 3) * 2;
            const int r0  = m0 + wm * 32 + mi * 16 + (lane >> 2);
            const int r1  = r0 + 8;
            const float b0 = bias[col], b1 = bias[col + 1];
            if (r0 < M) {
                float2 o = make_float2(acc[mi][nj][0] + b0, acc[mi][nj][1] + b1);
                if (res) {
                    const float2 rv = *(const float2*)(res + (size_t)r0 * N + col);
                    o.x += rv.x; o.y += rv.y;
                }
                *(float2*)(C + (size_t)r0 * N + col) = o;
            }
            if (r1 < M) {
                float2 o = make_float2(acc[mi][nj][2] + b0, acc[mi][nj][3] + b1);
                if (res) {
                    const float2 rv = *(const float2*)(res + (size_t)r1 * N + col);
                    o.x += rv.x; o.y += rv.y;
                }
                *(float2*)(C + (size_t)r1 * N + col) = o;
            }
        }
    }
}

// ---------------------------------------------------------------------------
// Sampler; reads SO/AWL from fused QA buffer (stride 384); emits [h|l] TMP.
// ---------------------------------------------------------------------------
__global__ __launch_bounds__(256) void msda_sample4(
    const float* __restrict__ V, const float* __restrict__ QA,
    const float* __restrict__ refp,
    const int* __restrict__ shapes, const int* __restrict__ starts,
    __nv_bfloat16* __restrict__ outCat, int M)
{
    __shared__ int4   sOff[4][16][8];
    __shared__ float4 sW  [4][16][8];

    const int tid = threadIdx.x;

    // Phase A
    {
        const int wi  = tid << 1;
        const int bqL = wi >> 7;
        const int h   = (wi >> 4) & 7;
        const int pt0 = wi & 15;
        int bq = blockIdx.x * 4 + bqL;
        bq = min(bq, M - 1);

        const float2 lg = *(const float2*)(QA + (size_t)bq * QASTR + 256 + h * 16 + pt0);
        float mx = fmaxf(lg.x, lg.y);
#pragma unroll
        for (int off = 4; off; off >>= 1)
            mx = fmaxf(mx, __shfl_xor_sync(0xffffffffu, mx, off));
        const float e0 = expf(lg.x - mx);
        const float e1 = expf(lg.y - mx);
        float sm = e0 + e1;
#pragma unroll
        for (int off = 4; off; off >>= 1)
            sm += __shfl_xor_sync(0xffffffffu, sm, off);
        const float inv = 1.f / sm;

        const int l = pt0 >> 2;
        const int H = shapes[2 * l + 0];
        const int W = shapes[2 * l + 1];
        const int st = starts[l];
        const float2 rp = *(const float2*)(refp + ((size_t)bq * NLVL + l) * 2);
        const float4 so = *(const float4*)(QA + (size_t)bq * QASTR + h * 32 + pt0 * 2);

#pragma unroll
        for (int k = 0; k < 2; k++) {
            const int pt = pt0 + k;
            const float aw  = (k ? e1 : e0) * inv;
            const float sox = k ? so.z : so.x;
            const float soy = k ? so.w : so.y;

            const float x = fmaf(rp.x, (float)W, sox) - 0.5f;
            const float y = fmaf(rp.y, (float)H, soy) - 0.5f;
            const float xf = floorf(x), yf = floorf(y);
            const int x0 = (int)xf, y0 = (int)yf;
            const float wx1 = x - xf, wx0 = 1.f - wx1;
            const float wy1 = y - yf, wy0 = 1.f - wy1;

            const bool vx0 = (x0 >= 0) && (x0 < W);
            const bool vx1 = (x0 + 1 >= 0) && (x0 + 1 < W);
            const bool vy0 = (y0 >= 0) && (y0 < H);
            const bool vy1 = (y0 + 1 >= 0) && (y0 + 1 < H);

            const int cx0 = max(0, min(x0,     W - 1));
            const int cx1 = max(0, min(x0 + 1, W - 1));
            const int cy0 = max(0, min(y0,     H - 1));
            const int cy1 = max(0, min(y0 + 1, H - 1));

            int4 o;
            o.x = st + cy0 * W + cx0;
            o.y = st + cy0 * W + cx1;
            o.z = st + cy1 * W + cx0;
            o.w = st + cy1 * W + cx1;

            float4 w4;
            w4.x = (vx0 && vy0) ? wx0 * wy0 * aw : 0.f;
            w4.y = (vx1 && vy0) ? wx1 * wy0 * aw : 0.f;
            w4.z = (vx0 && vy1) ? wx0 * wy1 * aw : 0.f;
            w4.w = (vx1 && vy1) ? wx1 * wy1 * aw : 0.f;

            sOff[bqL][pt][h] = o;
            sW  [bqL][pt][h] = w4;
        }
    }
    __syncthreads();

    // Phase B
    const int warpId = tid >> 5;
    const int lane   = tid & 31;
    const int bqL    = warpId >> 1;
    const int h      = ((warpId & 1) << 2) + (lane >> 3);
    const int c4     = lane & 7;
    const int bq     = blockIdx.x * 4 + bqL;
    if (bq >= M) return;
    const int b = bq / NQ;

    const float* vb = V + (size_t)b * NQ * EDIM + h * 32 + c4 * 4;

    float4 acc = make_float4(0.f, 0.f, 0.f, 0.f);
#pragma unroll
    for (int pt = 0; pt < 16; pt++) {
        const int4   o = sOff[bqL][pt][h];
        const float4 w = sW  [bqL][pt][h];

        const float4 v0 = *(const float4*)(vb + (size_t)o.x * EDIM);
        const float4 v1 = *(const float4*)(vb + (size_t)o.y * EDIM);
        const float4 v2 = *(const float4*)(vb + (size_t)o.z * EDIM);
        const float4 v3 = *(const float4*)(vb + (size_t)o.w * EDIM);

        acc.x = fmaf(w.x, v0.x, acc.x); acc.y = fmaf(w.x, v0.y, acc.y);
        acc.z = fmaf(w.x, v0.z, acc.z); acc.w = fmaf(w.x, v0.w, acc.w);
        acc.x = fmaf(w.y, v1.x, acc.x); acc.y = fmaf(w.y, v1.y, acc.y);
        acc.z = fmaf(w.y, v1.z, acc.z); acc.w = fmaf(w.y, v1.w, acc.w);
        acc.x = fmaf(w.z, v2.x, acc.x); acc.y = fmaf(w.z, v2.y, acc.y);
        acc.z = fmaf(w.z, v2.z, acc.z); acc.w = fmaf(w.z, v2.w, acc.w);
        acc.x = fmaf(w.w, v3.x, acc.x); acc.y = fmaf(w.w, v3.y, acc.y);
        acc.z = fmaf(w.w, v3.z, acc.z); acc.w = fmaf(w.w, v3.w, acc.w);
    }

    __nv_bfloat16 hh[4], ll[4];
    const float f[4] = {acc.x, acc.y, acc.z, acc.w};
#pragma unroll
    for (int k = 0; k < 4; k++) {
        hh[k] = __float2bfloat16(f[k]);
        ll[k] = __float2bfloat16(f[k] - __bfloat162float(hh[k]));
    }
    __nv_bfloat16* base = outCat + (size_t)bq * KP2 + h * 32 + c4 * 4;
    *(uint2*)(base)       = *(const uint2*)hh;
    *(uint2*)(base + 256) = *(const uint2*)ll;
}

// ---------------------------------------------------------------------------
// Launch
// ---------------------------------------------------------------------------
extern "C" void kernel_launch(void* const* d_in, const int* in_sizes, int n_in,
                              void* d_out, int out_size)
{
    const float* query  = (const float*)d_in[0];
    const float* value  = (const float*)d_in[1];
    const float* refp   = (const float*)d_in[2];
    const int*   shapes = (const int*)  d_in[3];
    const int*   starts = (const int*)  d_in[4];
    const float* Wv  = (const float*)d_in[5];
    const float* bv  = (const float*)d_in[6];
    const float* Wso = (const float*)d_in[7];
    const float* bso = (const float*)d_in[8];
    const float* Waw = (const float*)d_in[9];
    const float* baw = (const float*)d_in[10];
    const float* Wo  = (const float*)d_in[11];
    const float* bo  = (const float*)d_in[12];
    float* out = (float*)d_out;

    const int M = in_sizes[0] / EDIM;   // 40394

    float *pV, *pQA, *pBiasQA;
    __nv_bfloat16 *pAval, *pAq, *pAtmp, *pBv, *pBqa, *pBo;
    cudaGetSymbolAddress((void**)&pV,     g_V);
    cudaGetSymbolAddress((void**)&pQA,    g_QA);
    cudaGetSymbolAddress((void**)&pBiasQA,g_biasQA);
    cudaGetSymbolAddress((void**)&pAval,  g_Aval);
    cudaGetSymbolAddress((void**)&pAq,    g_Aq);
    cudaGetSymbolAddress((void**)&pAtmp,  g_Atmp);
    cudaGetSymbolAddress((void**)&pBv,    g_Bv);
    cudaGetSymbolAddress((void**)&pBqa,   g_Bqa);
    cudaGetSymbolAddress((void**)&pBo,    g_Bo);

    cudaFuncSetAttribute(gemm_mma, cudaFuncAttributeMaxDynamicSharedMemorySize, SMEM_GEMM);

    const int n4 = M * (EDIM / 4);
    const int cvtBlocks = (n4 + 255) / 256;
    const int mTiles = (M + 127) / 128;
    const dim3 g256(mTiles, 2);
    const dim3 g384(mTiles, 3);

    split_cat<<<cvtBlocks, 256>>>(value, pAval, n4);
    split_cat<<<cvtBlocks, 256>>>(query, pAq,   n4);
    prep_weights<<<(229760 + 255) / 256, 256>>>(Wv, Wso, Waw, Wo, bso, baw);

    gemm_mma<<<g256, 256, SMEM_GEMM>>>(pAval, pBv,  bv,      nullptr, pV,  M, 256);
    gemm_mma<<<g384, 256, SMEM_GEMM>>>(pAq,   pBqa, pBiasQA, nullptr, pQA, M, QASTR);
    msda_sample4<<<(M + 3) / 4, 256>>>(pV, pQA, refp, shapes, starts, pAtmp, M);
    gemm_mma<<<g256, 256, SMEM_GEMM>>>(pAtmp, pBo,  bo,      query,   out, M, 256);
}